// round 7
// baseline (speedup 1.0000x reference)
#include <cuda_runtime.h>
#include <math.h>

#define HID    256
#define CIN    128
#define COUT   128
#define BATCH  32
#define SEQ    4096
#define NROWS  (BATCH*SEQ)
#define CHUNKS 4
#define CHUNK_LEN (SEQ/CHUNKS)
#define WARM   512
#define ASPITCH 100
#define PITERS 120

// ---------------- device scratch (static globals; no runtime allocs) --------
__device__ float g_BA[HID*HID];
__device__ float g_BB[HID*HID];
__device__ float g_scale;
__device__ float g_AT [HID*HID];         // A_norm transposed: AT[k*HID+i] = A[i][k]*s
__device__ float g_WBT[CIN*HID];         // WBT[c*HID+h] = W_B[h][c]
__device__ float g_WCT[HID*COUT];        // WCT[h*COUT+o] = W_C[o][h]
__device__ float g_u [(size_t)NROWS*HID];
__device__ float g_hs[(size_t)NROWS*HID];

// ---------------- 1) B = A^T A ----------------------------------------------
__global__ void k_ata(const float* __restrict__ A) {
    __shared__ float col[HID];
    int i = blockIdx.x, j = threadIdx.x;
    col[j] = A[j*HID + i];
    __syncthreads();
    float a0=0.f,a1=0.f,a2=0.f,a3=0.f;
    #pragma unroll 16
    for (int k = 0; k < HID; k += 4) {
        a0 = fmaf(col[k+0], A[(k+0)*HID + j], a0);
        a1 = fmaf(col[k+1], A[(k+1)*HID + j], a1);
        a2 = fmaf(col[k+2], A[(k+2)*HID + j], a2);
        a3 = fmaf(col[k+3], A[(k+3)*HID + j], a3);
    }
    g_BA[i*HID + j] = (a0+a1)+(a2+a3);
}

// ---------------- 2) B <- B @ B (ping-pong; 7x => B^128) --------------------
__global__ void k_sq(int srcA) {
    const float* __restrict__ Bin = srcA ? g_BA : g_BB;
    float* __restrict__ Bout      = srcA ? g_BB : g_BA;
    __shared__ float row[HID];
    int i = blockIdx.x, j = threadIdx.x;
    row[j] = Bin[i*HID + j];
    __syncthreads();
    float a0=0.f,a1=0.f,a2=0.f,a3=0.f;
    #pragma unroll 16
    for (int k = 0; k < HID; k += 4) {
        a0 = fmaf(row[k+0], Bin[(k+0)*HID + j], a0);
        a1 = fmaf(row[k+1], Bin[(k+1)*HID + j], a1);
        a2 = fmaf(row[k+2], Bin[(k+2)*HID + j], a2);
        a3 = fmaf(row[k+3], Bin[(k+3)*HID + j], a3);
    }
    Bout[i*HID + j] = (a0+a1)+(a2+a3);
}

// ---------------- 3) power iteration on C = B^128 (in g_BB) -----------------
__device__ float red_sum(float v, float* red, int tid) {
    red[tid] = v; __syncthreads();
    for (int s = 128; s > 0; s >>= 1) { if (tid < s) red[tid] += red[tid+s]; __syncthreads(); }
    float r = red[0]; __syncthreads(); return r;
}
__device__ float red_max(float v, float* red, int tid) {
    red[tid] = v; __syncthreads();
    for (int s = 128; s > 0; s >>= 1) { if (tid < s) red[tid] = fmaxf(red[tid], red[tid+s]); __syncthreads(); }
    float r = red[0]; __syncthreads(); return r;
}
__global__ void k_power() {
    __shared__ float v[HID];
    __shared__ float red[HID];
    int tid = threadIdx.x;
    const float* __restrict__ C = g_BB;   // symmetric
    v[tid] = 1.0f;
    __syncthreads();
    float w = 0.f;
    for (int it = 0; it < PITERS; ++it) {
        float a0=0.f,a1=0.f,a2=0.f,a3=0.f;
        #pragma unroll 8
        for (int k = 0; k < HID; k += 4) {   // w[i] = sum_k C[k][i] v[k] (coalesced)
            a0 = fmaf(C[(k+0)*HID + tid], v[k+0], a0);
            a1 = fmaf(C[(k+1)*HID + tid], v[k+1], a1);
            a2 = fmaf(C[(k+2)*HID + tid], v[k+2], a2);
            a3 = fmaf(C[(k+3)*HID + tid], v[k+3], a3);
        }
        w = (a0+a1)+(a2+a3);
        float m = red_max(fabsf(w), red, tid);       // max-norm: no overflow
        float inv = 1.0f / m;
        v[tid] = w * inv;
        __syncthreads();
    }
    // final matvec + Rayleigh quotient
    {
        float a0=0.f,a1=0.f,a2=0.f,a3=0.f;
        #pragma unroll 8
        for (int k = 0; k < HID; k += 4) {
            a0 = fmaf(C[(k+0)*HID + tid], v[k+0], a0);
            a1 = fmaf(C[(k+1)*HID + tid], v[k+1], a1);
            a2 = fmaf(C[(k+2)*HID + tid], v[k+2], a2);
            a3 = fmaf(C[(k+3)*HID + tid], v[k+3], a3);
        }
        w = (a0+a1)+(a2+a3);
    }
    float num = red_sum(v[tid]*w,      red, tid);
    float den = red_sum(v[tid]*v[tid], red, tid);
    if (tid == 0) {
        double mu = (double)num / (double)den;       // ~ sigma^256
        double sigma = exp(log(mu) / 256.0);
        g_scale = (float)(1.0 / (sigma + 1e-5));
    }
}

// ---------------- 4) build AT (scaled), WBT, WCT ----------------------------
__global__ void k_prep(const float* __restrict__ A,
                       const float* __restrict__ WB,
                       const float* __restrict__ WC) {
    int k = blockIdx.x, t = threadIdx.x;         // grid 256, block 256
    float s = g_scale;
    g_AT[k*HID + t] = A[t*HID + k] * s;
    if (k < CIN)  g_WBT[k*HID + t]  = WB[t*CIN + k];
    if (t < COUT) g_WCT[k*COUT + t] = WC[t*HID + k];
}

// ---------------- 5) u projection: u = x @ W_B^T ----------------------------
// block = 256 threads (j = hidden idx), 32 rows per block
__global__ void __launch_bounds__(256) k_uproj(const float* __restrict__ x) {
    __shared__ float xs[CIN*36];                 // xs[k*36 + r]
    int tid = threadIdx.x;
    size_t row0 = (size_t)blockIdx.x * 32;
    for (int idx = tid; idx < 32*CIN; idx += 256) {
        int k = idx & 127, r = idx >> 7;
        xs[k*36 + r] = x[(row0 + r)*CIN + k];
    }
    __syncthreads();
    int j = tid;
    float acc[32];
    #pragma unroll
    for (int r = 0; r < 32; ++r) acc[r] = 0.f;
    #pragma unroll 2
    for (int k = 0; k < CIN; ++k) {
        float wb = g_WBT[k*HID + j];
        #pragma unroll
        for (int r = 0; r < 32; r += 4) {
            float4 xv = *(const float4*)&xs[k*36 + r];
            acc[r+0] = fmaf(wb, xv.x, acc[r+0]);
            acc[r+1] = fmaf(wb, xv.y, acc[r+1]);
            acc[r+2] = fmaf(wb, xv.z, acc[r+2]);
            acc[r+3] = fmaf(wb, xv.w, acc[r+3]);
        }
    }
    #pragma unroll
    for (int r = 0; r < 32; ++r) g_u[(row0 + r)*HID + j] = acc[r];
}

// ---------------- 6) recurrence: 128 CTAs = (chunk, batch) ------------------
// 512 threads: i = tid&255 (output row), half = tid>>8 (k-half).
// Per (i,half): 80 A-cols in registers, 48 from SMEM (pitch 100).
__global__ void __launch_bounds__(512,1) k_rec() {
    extern __shared__ float sm[];
    float* As   = sm;                      // 256*100
    float* h0   = sm + HID*ASPITCH;        // 256
    float* h1   = h0 + HID;                // 256
    float* psum = h1 + HID;                // 256
    const int tid  = threadIdx.x;
    const int i    = tid & 255;
    const int half = tid >> 8;
    const int kbase = half << 7;
    const int b     = blockIdx.x & 31;
    const int chunk = blockIdx.x >> 5;

    float areg[80];
    #pragma unroll
    for (int j = 0; j < 80; ++j) areg[j] = g_AT[(kbase + j)*HID + i];

    for (int idx = tid; idx < 96*256; idx += 512) {
        int i2 = idx & 255, kk = idx >> 8;                 // kk in [0,96)
        int k = (kk < 48) ? (80 + kk) : (160 + kk);        // half0: 80..127, half1: 208..255
        As[i2*ASPITCH + kk] = g_AT[k*HID + i2];
    }
    if (tid < HID) h0[tid] = 0.f;

    const int t0   = (chunk == 0) ? 0 : chunk*CHUNK_LEN - WARM;
    const int t1   = chunk*CHUNK_LEN;
    const int tend = (chunk + 1)*CHUNK_LEN;
    float unext = 0.f;
    if (!half) unext = g_u[((size_t)b*SEQ + t0)*HID + i];
    __syncthreads();

    float* hc = h0; float* hn = h1;
    const float* arow = As + i*ASPITCH + half*48;
    for (int t = t0; t < tend; ++t) {
        const float* h = hc + kbase;
        float a0=0.f,a1=0.f,a2=0.f,a3=0.f;
        #pragma unroll
        for (int j = 0; j < 80; j += 4) {
            float4 h4 = *(const float4*)(h + j);
            a0 = fmaf(areg[j+0], h4.x, a0);
            a1 = fmaf(areg[j+1], h4.y, a1);
            a2 = fmaf(areg[j+2], h4.z, a2);
            a3 = fmaf(areg[j+3], h4.w, a3);
        }
        #pragma unroll
        for (int j = 0; j < 48; j += 4) {
            float4 h4 = *(const float4*)(h + 80 + j);
            float4 a4 = *(const float4*)(arow + j);
            a0 = fmaf(a4.x, h4.x, a0);
            a1 = fmaf(a4.y, h4.y, a1);
            a2 = fmaf(a4.z, h4.z, a2);
            a3 = fmaf(a4.w, h4.w, a3);
        }
        float acc = (a0+a1)+(a2+a3);
        float ucur = unext;
        if (half) {
            psum[i] = acc;
        } else if (t + 1 < tend) {
            unext = g_u[((size_t)b*SEQ + t + 1)*HID + i];
        }
        __syncthreads();
        if (!half) {
            float hv = fmaxf(acc + psum[i] + ucur, 0.f);
            hn[i] = hv;
            if (t >= t1) g_hs[((size_t)b*SEQ + t)*HID + i] = hv;
        }
        __syncthreads();
        float* tmp = hc; hc = hn; hn = tmp;
    }
}

// ---------------- 7) y projection: y = hs @ W_C^T ---------------------------
// block = 256 threads: j = tid&127 (out col), rg = tid>>7; 32 rows per block
__global__ void __launch_bounds__(256) k_yproj(float* __restrict__ y) {
    __shared__ float hst[HID*36];                // hst[k*36 + r]
    int tid = threadIdx.x;
    size_t row0 = (size_t)blockIdx.x * 32;
    for (int idx = tid; idx < 32*HID; idx += 256) {
        int k = idx & 255, r = idx >> 8;
        hst[k*36 + r] = g_hs[(row0 + r)*HID + k];
    }
    __syncthreads();
    int j = tid & 127, rb = (tid >> 7) * 16;
    float acc[16];
    #pragma unroll
    for (int r = 0; r < 16; ++r) acc[r] = 0.f;
    #pragma unroll 2
    for (int k = 0; k < HID; ++k) {
        float wc = g_WCT[k*COUT + j];
        #pragma unroll
        for (int r = 0; r < 16; r += 4) {
            float4 hv = *(const float4*)&hst[k*36 + rb + r];
            acc[r+0] = fmaf(wc, hv.x, acc[r+0]);
            acc[r+1] = fmaf(wc, hv.y, acc[r+1]);
            acc[r+2] = fmaf(wc, hv.z, acc[r+2]);
            acc[r+3] = fmaf(wc, hv.w, acc[r+3]);
        }
    }
    #pragma unroll
    for (int r = 0; r < 16; ++r) y[(row0 + rb + r)*COUT + j] = acc[r];
}

// ---------------- launch ----------------------------------------------------
extern "C" void kernel_launch(void* const* d_in, const int* in_sizes, int n_in,
                              void* d_out, int out_size) {
    const float* x  = (const float*)d_in[0];
    const float* A  = (const float*)d_in[1];
    const float* WB = (const float*)d_in[2];
    const float* WC = (const float*)d_in[3];
    float* y = (float*)d_out;

    static const int REC_SMEM = (HID*ASPITCH + 3*HID) * 4;  // 105472 B
    cudaFuncSetAttribute(k_rec, cudaFuncAttributeMaxDynamicSharedMemorySize, REC_SMEM);

    k_ata<<<HID, HID>>>(A);
    k_sq<<<HID, HID>>>(1);   // BA -> BB
    k_sq<<<HID, HID>>>(0);   // BB -> BA
    k_sq<<<HID, HID>>>(1);
    k_sq<<<HID, HID>>>(0);
    k_sq<<<HID, HID>>>(1);
    k_sq<<<HID, HID>>>(0);
    k_sq<<<HID, HID>>>(1);   // 7th: BA -> BB  (C = B^128 in g_BB)
    k_power<<<1, HID>>>();
    k_prep<<<HID, HID>>>(A, WB, WC);
    k_uproj<<<NROWS/32, 256>>>(x);
    k_rec<<<CHUNKS*BATCH, 512, REC_SMEM>>>();
    k_yproj<<<NROWS/32, 256>>>(y);
}